// round 4
// baseline (speedup 1.0000x reference)
#include <cuda_runtime.h>
#include <math_constants.h>

#define BATCH 64
#define N 1024
#define RBLKS 16            // row-blocks per batch (64 rows each)

// Scratch: row offsets R[b][i], col offsets C[b][j], per-CTA column partials
__device__ float g_R[BATCH * N];
__device__ float g_C[BATCH * N];
__device__ float g_part[BATCH * RBLKS * N];   // 4 MB

// ---------------------------------------------------------------------------
// Fused pass (one read of s does a row iteration AND a column iteration):
//   per row i:  sum_i = sum_j exp(s[i][j] - C[j]);  R[i] = log(sum_i)
//   column partials: part[j] += sum_i exp(s[i][j] - C[j] - R[i])
// finalize_col forms C_new[j] = log(sum_blocks part) + C_old[j].
// Warp-per-row, 8 rows per warp, column partials accumulated in REGISTERS
// (lane<->column mapping fixed), single smem reduce at CTA end.
// grid = (RBLKS, BATCH), block = 256 (8 warps).
// ---------------------------------------------------------------------------
template <bool USE_C>
__global__ void __launch_bounds__(256) fused_pass(const float* __restrict__ s) {
    __shared__ float c_s[N];
    __shared__ float stage[8 * N];     // 32 KB, used once at the end
    const int b = blockIdx.y;
    if (USE_C) {
        #pragma unroll
        for (int t = threadIdx.x; t < N; t += 256) c_s[t] = g_C[b * N + t];
        __syncthreads();
    }

    const int warp = threadIdx.x >> 5;
    const int lane = threadIdx.x & 31;
    const int tid  = threadIdx.x;

    float cacc[32];
    #pragma unroll
    for (int k = 0; k < 32; k++) cacc[k] = 0.f;

    #pragma unroll 1
    for (int g = 0; g < 8; g++) {
        const int row = (blockIdx.x << 6) + (g << 3) + warp;
        const float* p = s + ((size_t)b << 20) + ((size_t)row << 10);

        float e[32];
        float sum = 0.f;
        #pragma unroll
        for (int k = 0; k < 8; k++) {
            const int j = (lane << 2) + (k << 7);
            float4 sv = __ldcs(reinterpret_cast<const float4*>(p + j));
            if (USE_C) {
                float4 cv = *reinterpret_cast<const float4*>(&c_s[j]);
                sv.x -= cv.x; sv.y -= cv.y; sv.z -= cv.z; sv.w -= cv.w;
            }
            e[4*k+0] = __expf(sv.x); e[4*k+1] = __expf(sv.y);
            e[4*k+2] = __expf(sv.z); e[4*k+3] = __expf(sv.w);
            sum += (e[4*k+0] + e[4*k+1]) + (e[4*k+2] + e[4*k+3]);
        }
        #pragma unroll
        for (int off = 16; off; off >>= 1)
            sum += __shfl_xor_sync(0xffffffffu, sum, off);

        if (lane == 0) g_R[b * N + row] = logf(sum);  // final pass's R feeds out_pass
        const float rinv = 1.f / sum;

        // column partials in registers: exp(v - R) = e[k] * rinv
        #pragma unroll
        for (int k = 0; k < 32; k++) cacc[k] = fmaf(e[k], rinv, cacc[k]);
    }

    // single cross-warp reduce of column partials
    #pragma unroll
    for (int k = 0; k < 8; k++) {
        const int j = (lane << 2) + (k << 7);
        float4 v = make_float4(cacc[4*k+0], cacc[4*k+1], cacc[4*k+2], cacc[4*k+3]);
        *reinterpret_cast<float4*>(&stage[warp * N + j]) = v;
    }
    __syncthreads();

    float4 a = make_float4(0.f, 0.f, 0.f, 0.f);
    #pragma unroll
    for (int w = 0; w < 8; w++) {
        float4 sv = *reinterpret_cast<const float4*>(&stage[w * N + (tid << 2)]);
        a.x += sv.x; a.y += sv.y; a.z += sv.z; a.w += sv.w;
    }
    __stcs(reinterpret_cast<float4*>(
               &g_part[((size_t)(b * RBLKS + blockIdx.x)) * N]) + tid, a);
}

// ---------------------------------------------------------------------------
// Finalize: C_new[b][j] = log( sum over RBLKS row-block partials ) + C_old.
// FIRST=true: pass ran with C==0 -> write log(sum) directly (must NOT read
// g_C: it holds stale values from the previous graph replay).
// float4 per thread, 16-deep MLP. grid = BATCH*N/4/256 = 64 CTAs.
// ---------------------------------------------------------------------------
template <bool FIRST>
__global__ void __launch_bounds__(256) finalize_col() {
    const int q = blockIdx.x * 256 + threadIdx.x;     // float4 index into [b][j]
    const int b = q >> 8;                             // 256 float4 per row of N
    float4 sum = make_float4(0.f, 0.f, 0.f, 0.f);
    #pragma unroll
    for (int r = 0; r < RBLKS; r++) {
        float4 v = __ldcs(reinterpret_cast<const float4*>(
            &g_part[((size_t)(b * RBLKS + r)) * N]) + (q & 255));
        sum.x += v.x; sum.y += v.y; sum.z += v.z; sum.w += v.w;
    }
    float4* c4 = reinterpret_cast<float4*>(g_C) + q;
    if (FIRST) {
        *c4 = make_float4(logf(sum.x), logf(sum.y), logf(sum.z), logf(sum.w));
    } else {
        float4 c = *c4;
        *c4 = make_float4(logf(sum.x) + c.x, logf(sum.y) + c.y,
                          logf(sum.z) + c.z, logf(sum.w) + c.w);
    }
}

// ---------------------------------------------------------------------------
// Output pass: out = exp(s - R[b][i] - C[b][j]), float4, streaming hints.
// ---------------------------------------------------------------------------
__global__ void __launch_bounds__(256) out_pass(const float4* __restrict__ s4,
                                                float4* __restrict__ o4) {
    const size_t gid  = (size_t)blockIdx.x * 256 + threadIdx.x;
    const size_t base = gid << 2;
    const int b = (int)(base >> 20);
    const int i = (int)(base >> 10) & (N - 1);
    const int j = (int)base & (N - 1);
    const float r = __ldg(&g_R[(b << 10) + i]);
    const float4 c = *reinterpret_cast<const float4*>(&g_C[(b << 10) + j]);
    float4 v = __ldcs(s4 + gid);
    float4 o;
    o.x = __expf(v.x - r - c.x);
    o.y = __expf(v.y - r - c.y);
    o.z = __expf(v.z - r - c.z);
    o.w = __expf(v.w - r - c.w);
    __stcs(o4 + gid, o);
}

// ---------------------------------------------------------------------------
extern "C" void kernel_launch(void* const* d_in, const int* in_sizes, int n_in,
                              void* d_out, int out_size) {
    const float* s = (const float*)d_in[0];
    float* out = (float*)d_out;

    const dim3 fgrid(RBLKS, BATCH);
    const int fin_blocks = BATCH * N / 4 / 256;       // 64
    const int out_blocks = (BATCH * N * N / 4) / 256;

    // iters 0+1
    fused_pass<false><<<fgrid, 256>>>(s);
    finalize_col<true><<<fin_blocks, 256>>>();
    // iters 2+3, 4+5, 6+7, 8+9
    fused_pass<true><<<fgrid, 256>>>(s);
    finalize_col<false><<<fin_blocks, 256>>>();
    fused_pass<true><<<fgrid, 256>>>(s);
    finalize_col<false><<<fin_blocks, 256>>>();
    fused_pass<true><<<fgrid, 256>>>(s);
    finalize_col<false><<<fin_blocks, 256>>>();
    fused_pass<true><<<fgrid, 256>>>(s);
    finalize_col<false><<<fin_blocks, 256>>>();

    out_pass<<<out_blocks, 256>>>((const float4*)s, (float4*)out);
}